// round 1
// baseline (speedup 1.0000x reference)
#include <cuda_runtime.h>
#include <math.h>

#define N_NODES 50000
#define N_EDGES 800000
#define HID     128
#define OUT_DIM 40
#define N_LAYERS 4
#define N_GRAPHS 128

// ---------------- scratch (static device globals; no allocation) ----------------
__device__ float g_A[N_NODES * HID];
__device__ float g_B[N_NODES * HID];
__device__ float g_C[N_NODES * HID];
__device__ int   g_rowoff[N_NODES + 1];
__device__ int   g_cursor[N_NODES];
__device__ int   g_srcs[N_EDGES];
__device__ int   g_is64;
__device__ float g_pooled[N_GRAPHS * HID];
__device__ float g_bnscale[HID];
__device__ float g_bnshift[HID];

// ---------------- index dtype handling ----------------
__device__ __forceinline__ long long load_idx(const void* p, long long i, int is64) {
    if (is64) return ((const long long*)p)[i];
    return (long long)((const int*)p)[i];
}

// Detect whether edge_index is int64 or int32. For int32 data reinterpreted
// as int64, the high word is a random node id (nonzero w.p. ~1-2e-5), so 64
// samples all being valid node ids implies genuine int64.
__global__ void k_detect(const void* __restrict__ edge) {
    if (threadIdx.x == 0) {
        const long long* p = (const long long*)edge;
        int ok = 1;
        for (int i = 0; i < 64; i++) {
            long long v = p[(long long)i * 12347 + 5];   // max idx 777866 < 800000
            if (v < 0 || v >= N_NODES) ok = 0;
        }
        g_is64 = ok;
    }
}

__global__ void k_zero_int(int* p, int n) {
    int i = blockIdx.x * blockDim.x + threadIdx.x;
    if (i < n) p[i] = 0;
}

// ---------------- CSR build (by dst) ----------------
__global__ void k_count(const void* __restrict__ edge) {
    int e = blockIdx.x * blockDim.x + threadIdx.x;
    if (e >= N_EDGES) return;
    int is64 = g_is64;
    int dst = (int)load_idx(edge, (long long)N_EDGES + e, is64);
    atomicAdd(&g_rowoff[dst], 1);
}

// single-block exclusive scan of counts -> offsets (+ cursor init)
__global__ void k_scan() {
    __shared__ int part[1024];
    const int CH = (N_NODES + 1023) / 1024;  // 49
    int t = threadIdx.x;
    int s = 0;
    for (int i = 0; i < CH; i++) {
        int idx = t * CH + i;
        if (idx < N_NODES) s += g_rowoff[idx];
    }
    part[t] = s;
    __syncthreads();
    for (int off = 1; off < 1024; off <<= 1) {
        int v = (t >= off) ? part[t - off] : 0;
        __syncthreads();
        part[t] += v;
        __syncthreads();
    }
    int excl = part[t] - s;
    int run = excl;
    for (int i = 0; i < CH; i++) {
        int idx = t * CH + i;
        if (idx < N_NODES) {
            int c = g_rowoff[idx];
            g_rowoff[idx] = run;
            g_cursor[idx] = run;
            run += c;
        }
    }
    if (t == 0) g_rowoff[N_NODES] = N_EDGES;
}

__global__ void k_fill(const void* __restrict__ edge) {
    int e = blockIdx.x * blockDim.x + threadIdx.x;
    if (e >= N_EDGES) return;
    int is64 = g_is64;
    int src = (int)load_idx(edge, e, is64);
    int dst = (int)load_idx(edge, (long long)N_EDGES + e, is64);
    int pos = atomicAdd(&g_cursor[dst], 1);
    g_srcs[pos] = src;
}

// ---------------- aggregation: h[n] = (1+eps)*x[n] + sum_{src->n} x[src] ----------------
// warp per node, float4 per lane (128 floats / 32 lanes), no float atomics.
__global__ void k_agg(const float* __restrict__ xin, float* __restrict__ hout,
                      const float* __restrict__ eps_arr, int layer) {
    int w = (blockIdx.x * blockDim.x + threadIdx.x) >> 5;
    int lane = threadIdx.x & 31;
    if (w >= N_NODES) return;
    float eps = 1.0f + eps_arr[layer];
    const float4* x4 = (const float4*)xin;
    float4 a = x4[(long long)w * 32 + lane];
    float ax = a.x * eps, ay = a.y * eps, az = a.z * eps, aw = a.w * eps;
    int e = g_rowoff[w], end = g_rowoff[w + 1];
    for (; e + 3 < end; e += 4) {
        int s0 = g_srcs[e], s1 = g_srcs[e + 1], s2 = g_srcs[e + 2], s3 = g_srcs[e + 3];
        float4 v0 = x4[(long long)s0 * 32 + lane];
        float4 v1 = x4[(long long)s1 * 32 + lane];
        float4 v2 = x4[(long long)s2 * 32 + lane];
        float4 v3 = x4[(long long)s3 * 32 + lane];
        ax += (v0.x + v1.x) + (v2.x + v3.x);
        ay += (v0.y + v1.y) + (v2.y + v3.y);
        az += (v0.z + v1.z) + (v2.z + v3.z);
        aw += (v0.w + v1.w) + (v2.w + v3.w);
    }
    for (; e < end; e++) {
        int s = g_srcs[e];
        float4 v = x4[(long long)s * 32 + lane];
        ax += v.x; ay += v.y; az += v.z; aw += v.w;
    }
    float4 r; r.x = ax; r.y = ay; r.z = az; r.w = aw;
    ((float4*)hout)[(long long)w * 32 + lane] = r;
}

// ---------------- BN scale/shift precompute ----------------
__global__ void k_bnprep(const float* __restrict__ gamma, const float* __restrict__ beta,
                         const float* __restrict__ mean,  const float* __restrict__ var) {
    int t = threadIdx.x;
    if (t < HID) {
        float sc = gamma[t] * rsqrtf(var[t] + 1e-5f);
        g_bnscale[t] = sc;
        g_bnshift[t] = beta[t] - mean[t] * sc;
    }
}

// ---------------- fp32 GEMM: out = epi(A[N,128] @ W[128,128] + b) ----------------
// BM=64 rows/block, full K=128 staged. W resident in smem (64 KB), A tile
// transposed into smem with stride 68 (16B-aligned float4 rows, broadcast reads).
// 256 threads; thread tile 8 rows x 4 cols.
#define GBM 64
#define APAD 68
#define GEMM_SMEM ((128 * APAD + 128 * 128) * 4)

__global__ void k_gemm(const float* __restrict__ A, const float* __restrict__ W,
                       const float* __restrict__ bias, float* __restrict__ out,
                       const float* __restrict__ bnscale, const float* __restrict__ bnshift) {
    extern __shared__ float smem[];
    float* sAT = smem;                 // [128][APAD]
    float* sW  = smem + 128 * APAD;    // [128][128]
    int tid = threadIdx.x;
    int row0 = blockIdx.x * GBM;

    // stage W (4096 float4, 16 per thread)
    const float4* W4 = (const float4*)W;
    float4* sW4 = (float4*)sW;
    #pragma unroll
    for (int i = 0; i < 16; i++) sW4[tid + i * 256] = W4[tid + i * 256];

    // stage A tile, transposed (zero-pad out-of-range rows)
    #pragma unroll
    for (int it = 0; it < 8; it++) {
        int i = tid + it * 256;            // 0..2047 float4s
        int r = i >> 5;                    // row within tile
        int c4 = i & 31;                   // float4 column
        float4 v = make_float4(0.f, 0.f, 0.f, 0.f);
        if (row0 + r < N_NODES) v = ((const float4*)A)[(long long)(row0 + r) * 32 + c4];
        int kk = c4 * 4;
        sAT[(kk + 0) * APAD + r] = v.x;
        sAT[(kk + 1) * APAD + r] = v.y;
        sAT[(kk + 2) * APAD + r] = v.z;
        sAT[(kk + 3) * APAD + r] = v.w;
    }
    __syncthreads();

    int tx = tid & 31, ty = tid >> 5;
    int rbase = ty * 8, cbase = tx * 4;
    float acc[8][4];
    #pragma unroll
    for (int i = 0; i < 8; i++)
        #pragma unroll
        for (int j = 0; j < 4; j++) acc[i][j] = 0.f;

    #pragma unroll 16
    for (int k = 0; k < 128; k++) {
        float a[8];
        *(float4*)&a[0] = *(float4*)&sAT[k * APAD + rbase];
        *(float4*)&a[4] = *(float4*)&sAT[k * APAD + rbase + 4];
        float4 b = *(float4*)&sW[k * 128 + cbase];
        #pragma unroll
        for (int i = 0; i < 8; i++) {
            acc[i][0] += a[i] * b.x;
            acc[i][1] += a[i] * b.y;
            acc[i][2] += a[i] * b.z;
            acc[i][3] += a[i] * b.w;
        }
    }

    float4 bv = *(const float4*)&bias[cbase];
    float4 sc = make_float4(1.f, 1.f, 1.f, 1.f), sh = make_float4(0.f, 0.f, 0.f, 0.f);
    bool bn = (bnscale != nullptr);
    if (bn) {
        sc = *(const float4*)&bnscale[cbase];
        sh = *(const float4*)&bnshift[cbase];
    }
    #pragma unroll
    for (int i = 0; i < 8; i++) {
        int r = row0 + rbase + i;
        if (r >= N_NODES) continue;
        float4 o;
        o.x = fmaxf(acc[i][0] + bv.x, 0.f);
        o.y = fmaxf(acc[i][1] + bv.y, 0.f);
        o.z = fmaxf(acc[i][2] + bv.z, 0.f);
        o.w = fmaxf(acc[i][3] + bv.w, 0.f);
        if (bn) {
            o.x = o.x * sc.x + sh.x;
            o.y = o.y * sc.y + sh.y;
            o.z = o.z * sc.z + sh.z;
            o.w = o.w * sc.w + sh.w;
        }
        ((float4*)out)[(long long)r * 32 + tx] = o;
    }
}

// ---------------- mean pool per graph (batch sorted) ----------------
__device__ __forceinline__ int lower_bound_batch(const void* batch, long long key, int is64) {
    int lo = 0, hi = N_NODES;
    while (lo < hi) {
        int mid = (lo + hi) >> 1;
        long long v = load_idx(batch, mid, is64);
        if (v < key) lo = mid + 1; else hi = mid;
    }
    return lo;
}

__global__ void k_pool(const float* __restrict__ x, const void* __restrict__ batch) {
    int g = blockIdx.x;
    int f = threadIdx.x;
    __shared__ int s_beg, s_end;
    if (f == 0) {
        int is64 = g_is64;
        s_beg = lower_bound_batch(batch, g, is64);
        s_end = lower_bound_batch(batch, g + 1, is64);
    }
    __syncthreads();
    int beg = s_beg, end = s_end;
    float s = 0.f;
    for (int r = beg; r < end; r++) s += x[(long long)r * HID + f];
    float cnt = (float)(end - beg);
    g_pooled[g * HID + f] = s / fmaxf(cnt, 1.0f);
}

// ---------------- head: relu(pooled@W1+b1) @ W2 + b2, log_softmax ----------------
__global__ void k_head(const float* __restrict__ W1, const float* __restrict__ b1,
                       const float* __restrict__ W2, const float* __restrict__ b2,
                       float* __restrict__ out) {
    int g = blockIdx.x;
    int t = threadIdx.x;
    __shared__ float sp[HID], sh[HID], sl[OUT_DIM];
    __shared__ float smax, slse;
    sp[t] = g_pooled[g * HID + t];
    __syncthreads();
    float acc = b1[t];
    #pragma unroll 8
    for (int k = 0; k < HID; k++) acc += sp[k] * W1[k * HID + t];
    sh[t] = fmaxf(acc, 0.f);
    __syncthreads();
    if (t < OUT_DIM) {
        float a = b2[t];
        #pragma unroll 8
        for (int k = 0; k < HID; k++) a += sh[k] * W2[k * OUT_DIM + t];
        sl[t] = a;
    }
    __syncthreads();
    if (t == 0) {
        float m = -1e30f;
        for (int o = 0; o < OUT_DIM; o++) m = fmaxf(m, sl[o]);
        float s = 0.f;
        for (int o = 0; o < OUT_DIM; o++) s += expf(sl[o] - m);
        smax = m; slse = logf(s);
    }
    __syncthreads();
    if (t < OUT_DIM) out[g * OUT_DIM + t] = sl[t] - smax - slse;
}

// ---------------- launch ----------------
extern "C" void kernel_launch(void* const* d_in, const int* in_sizes, int n_in,
                              void* d_out, int out_size) {
    const float* x      = (const float*)d_in[0];
    const void*  edge   = d_in[1];
    const void*  batch  = d_in[2];
    const float* W1s    = (const float*)d_in[3];
    const float* b1s    = (const float*)d_in[4];
    const float* W2s    = (const float*)d_in[5];
    const float* b2s    = (const float*)d_in[6];
    const float* gammas = (const float*)d_in[7];
    const float* betas  = (const float*)d_in[8];
    const float* means  = (const float*)d_in[9];
    const float* vars   = (const float*)d_in[10];
    const float* epsarr = (const float*)d_in[11];
    const float* lin1W  = (const float*)d_in[12];
    const float* lin1b  = (const float*)d_in[13];
    const float* lin2W  = (const float*)d_in[14];
    const float* lin2b  = (const float*)d_in[15];
    float* out = (float*)d_out;

    float *A, *B, *C, *bnsc, *bnsh;
    int *rowoff;
    cudaGetSymbolAddress((void**)&A, g_A);
    cudaGetSymbolAddress((void**)&B, g_B);
    cudaGetSymbolAddress((void**)&C, g_C);
    cudaGetSymbolAddress((void**)&bnsc, g_bnscale);
    cudaGetSymbolAddress((void**)&bnsh, g_bnshift);
    cudaGetSymbolAddress((void**)&rowoff, g_rowoff);

    cudaFuncSetAttribute(k_gemm, cudaFuncAttributeMaxDynamicSharedMemorySize, GEMM_SMEM);

    // index width + CSR build (once per call)
    k_detect<<<1, 32>>>(edge);
    k_zero_int<<<(N_NODES + 1 + 255) / 256, 256>>>(rowoff, N_NODES + 1);
    k_count<<<(N_EDGES + 255) / 256, 256>>>(edge);
    k_scan<<<1, 1024>>>();
    k_fill<<<(N_EDGES + 255) / 256, 256>>>(edge);

    const int gemm_grid = (N_NODES + GBM - 1) / GBM;
    const int agg_blocks = (N_NODES * 32 + 255) / 256;

    const float* cur = x;
    for (int l = 0; l < N_LAYERS; l++) {
        k_agg<<<agg_blocks, 256>>>(cur, B, epsarr, l);
        k_gemm<<<gemm_grid, 256, GEMM_SMEM>>>(B, W1s + l * HID * HID, b1s + l * HID,
                                              C, nullptr, nullptr);
        k_bnprep<<<1, 128>>>(gammas + l * HID, betas + l * HID,
                             means + l * HID, vars + l * HID);
        k_gemm<<<gemm_grid, 256, GEMM_SMEM>>>(C, W2s + l * HID * HID, b2s + l * HID,
                                              A, bnsc, bnsh);
        cur = A;
    }

    k_pool<<<N_GRAPHS, HID>>>(A, batch);
    k_head<<<N_GRAPHS, HID>>>(lin1W, lin1b, lin2W, lin2b, out);
}

// round 2
// speedup vs baseline: 1.0046x; 1.0046x over previous
#include <cuda_runtime.h>
#include <math.h>

#define N_NODES 50000
#define N_EDGES 800000
#define HID     128
#define OUT_DIM 40
#define N_LAYERS 4
#define N_GRAPHS 128

// ---------------- scratch (static device globals; no allocation) ----------------
__device__ float g_A[N_NODES * HID];
__device__ float g_B[N_NODES * HID];
__device__ float g_C[N_NODES * HID];
__device__ int   g_rowoff[N_NODES + 1];
__device__ int   g_cursor[N_NODES];
__device__ int   g_srcs[N_EDGES];
__device__ int   g_is64;
__device__ float g_pooled[N_GRAPHS * HID];
__device__ float g_bnscale[HID];
__device__ float g_bnshift[HID];

// ---------------- index dtype handling ----------------
__device__ __forceinline__ long long load_idx(const void* p, long long i, int is64) {
    if (is64) return ((const long long*)p)[i];
    return (long long)((const int*)p)[i];
}

// Detect whether edge_index is int64 or int32. For int32 data reinterpreted
// as int64, the high word is a random node id (nonzero w.p. ~1-2e-5), so 64
// samples all being valid node ids implies genuine int64.
__global__ void k_detect(const void* __restrict__ edge) {
    if (threadIdx.x == 0) {
        const long long* p = (const long long*)edge;
        int ok = 1;
        for (int i = 0; i < 64; i++) {
            long long v = p[(long long)i * 12347 + 5];   // max idx 777866 < 800000
            if (v < 0 || v >= N_NODES) ok = 0;
        }
        g_is64 = ok;
    }
}

__global__ void k_zero_int(int* p, int n) {
    int i = blockIdx.x * blockDim.x + threadIdx.x;
    if (i < n) p[i] = 0;
}

// ---------------- CSR build (by dst) ----------------
__global__ void k_count(const void* __restrict__ edge) {
    int e = blockIdx.x * blockDim.x + threadIdx.x;
    if (e >= N_EDGES) return;
    int is64 = g_is64;
    int dst = (int)load_idx(edge, (long long)N_EDGES + e, is64);
    atomicAdd(&g_rowoff[dst], 1);
}

// single-block exclusive scan of counts -> offsets (+ cursor init)
__global__ void k_scan() {
    __shared__ int part[1024];
    const int CH = (N_NODES + 1023) / 1024;  // 49
    int t = threadIdx.x;
    int s = 0;
    for (int i = 0; i < CH; i++) {
        int idx = t * CH + i;
        if (idx < N_NODES) s += g_rowoff[idx];
    }
    part[t] = s;
    __syncthreads();
    for (int off = 1; off < 1024; off <<= 1) {
        int v = (t >= off) ? part[t - off] : 0;
        __syncthreads();
        part[t] += v;
        __syncthreads();
    }
    int excl = part[t] - s;
    int run = excl;
    for (int i = 0; i < CH; i++) {
        int idx = t * CH + i;
        if (idx < N_NODES) {
            int c = g_rowoff[idx];
            g_rowoff[idx] = run;
            g_cursor[idx] = run;
            run += c;
        }
    }
    if (t == 0) g_rowoff[N_NODES] = N_EDGES;
}

__global__ void k_fill(const void* __restrict__ edge) {
    int e = blockIdx.x * blockDim.x + threadIdx.x;
    if (e >= N_EDGES) return;
    int is64 = g_is64;
    int src = (int)load_idx(edge, e, is64);
    int dst = (int)load_idx(edge, (long long)N_EDGES + e, is64);
    int pos = atomicAdd(&g_cursor[dst], 1);
    g_srcs[pos] = src;
}

// ---------------- aggregation: h[n] = (1+eps)*x[n] + sum_{src->n} x[src] ----------------
// warp per node, float4 per lane (128 floats / 32 lanes), no float atomics.
__global__ void k_agg(const float* __restrict__ xin, float* __restrict__ hout,
                      const float* __restrict__ eps_arr, int layer) {
    int w = (blockIdx.x * blockDim.x + threadIdx.x) >> 5;
    int lane = threadIdx.x & 31;
    if (w >= N_NODES) return;
    float eps = 1.0f + eps_arr[layer];
    const float4* x4 = (const float4*)xin;
    float4 a = x4[(long long)w * 32 + lane];
    float ax = a.x * eps, ay = a.y * eps, az = a.z * eps, aw = a.w * eps;
    int e = g_rowoff[w], end = g_rowoff[w + 1];
    for (; e + 3 < end; e += 4) {
        int s0 = g_srcs[e], s1 = g_srcs[e + 1], s2 = g_srcs[e + 2], s3 = g_srcs[e + 3];
        float4 v0 = x4[(long long)s0 * 32 + lane];
        float4 v1 = x4[(long long)s1 * 32 + lane];
        float4 v2 = x4[(long long)s2 * 32 + lane];
        float4 v3 = x4[(long long)s3 * 32 + lane];
        ax += (v0.x + v1.x) + (v2.x + v3.x);
        ay += (v0.y + v1.y) + (v2.y + v3.y);
        az += (v0.z + v1.z) + (v2.z + v3.z);
        aw += (v0.w + v1.w) + (v2.w + v3.w);
    }
    for (; e < end; e++) {
        int s = g_srcs[e];
        float4 v = x4[(long long)s * 32 + lane];
        ax += v.x; ay += v.y; az += v.z; aw += v.w;
    }
    float4 r; r.x = ax; r.y = ay; r.z = az; r.w = aw;
    ((float4*)hout)[(long long)w * 32 + lane] = r;
}

// ---------------- BN scale/shift precompute ----------------
__global__ void k_bnprep(const float* __restrict__ gamma, const float* __restrict__ beta,
                         const float* __restrict__ mean,  const float* __restrict__ var) {
    int t = threadIdx.x;
    if (t < HID) {
        float sc = gamma[t] * rsqrtf(var[t] + 1e-5f);
        g_bnscale[t] = sc;
        g_bnshift[t] = beta[t] - mean[t] * sc;
    }
}

// ---------------- fp32 GEMM: out = epi(A[N,128] @ W[128,128] + b) ----------------
// BM=64 rows/block, full K=128 staged. W resident in smem (64 KB), A tile
// transposed into smem with stride 68 (16B-aligned float4 rows, broadcast reads).
// 256 threads; thread tile 8 rows x 4 cols.
#define GBM 64
#define APAD 68
#define GEMM_SMEM ((128 * APAD + 128 * 128) * 4)

__global__ void k_gemm(const float* __restrict__ A, const float* __restrict__ W,
                       const float* __restrict__ bias, float* __restrict__ out,
                       const float* __restrict__ bnscale, const float* __restrict__ bnshift) {
    extern __shared__ float smem[];
    float* sAT = smem;                 // [128][APAD]
    float* sW  = smem + 128 * APAD;    // [128][128]
    int tid = threadIdx.x;
    int row0 = blockIdx.x * GBM;

    // stage W (4096 float4, 16 per thread)
    const float4* W4 = (const float4*)W;
    float4* sW4 = (float4*)sW;
    #pragma unroll
    for (int i = 0; i < 16; i++) sW4[tid + i * 256] = W4[tid + i * 256];

    // stage A tile, transposed (zero-pad out-of-range rows)
    #pragma unroll
    for (int it = 0; it < 8; it++) {
        int i = tid + it * 256;            // 0..2047 float4s
        int r = i >> 5;                    // row within tile
        int c4 = i & 31;                   // float4 column
        float4 v = make_float4(0.f, 0.f, 0.f, 0.f);
        if (row0 + r < N_NODES) v = ((const float4*)A)[(long long)(row0 + r) * 32 + c4];
        int kk = c4 * 4;
        sAT[(kk + 0) * APAD + r] = v.x;
        sAT[(kk + 1) * APAD + r] = v.y;
        sAT[(kk + 2) * APAD + r] = v.z;
        sAT[(kk + 3) * APAD + r] = v.w;
    }
    __syncthreads();

    int tx = tid & 31, ty = tid >> 5;
    int rbase = ty * 8, cbase = tx * 4;
    float acc[8][4];
    #pragma unroll
    for (int i = 0; i < 8; i++)
        #pragma unroll
        for (int j = 0; j < 4; j++) acc[i][j] = 0.f;

    #pragma unroll 16
    for (int k = 0; k < 128; k++) {
        float a[8];
        *(float4*)&a[0] = *(float4*)&sAT[k * APAD + rbase];
        *(float4*)&a[4] = *(float4*)&sAT[k * APAD + rbase + 4];
        float4 b = *(float4*)&sW[k * 128 + cbase];
        #pragma unroll
        for (int i = 0; i < 8; i++) {
            acc[i][0] += a[i] * b.x;
            acc[i][1] += a[i] * b.y;
            acc[i][2] += a[i] * b.z;
            acc[i][3] += a[i] * b.w;
        }
    }

    float4 bv = *(const float4*)&bias[cbase];
    float4 sc = make_float4(1.f, 1.f, 1.f, 1.f), sh = make_float4(0.f, 0.f, 0.f, 0.f);
    bool bn = (bnscale != nullptr);
    if (bn) {
        sc = *(const float4*)&bnscale[cbase];
        sh = *(const float4*)&bnshift[cbase];
    }
    #pragma unroll
    for (int i = 0; i < 8; i++) {
        int r = row0 + rbase + i;
        if (r >= N_NODES) continue;
        float4 o;
        o.x = fmaxf(acc[i][0] + bv.x, 0.f);
        o.y = fmaxf(acc[i][1] + bv.y, 0.f);
        o.z = fmaxf(acc[i][2] + bv.z, 0.f);
        o.w = fmaxf(acc[i][3] + bv.w, 0.f);
        if (bn) {
            o.x = o.x * sc.x + sh.x;
            o.y = o.y * sc.y + sh.y;
            o.z = o.z * sc.z + sh.z;
            o.w = o.w * sc.w + sh.w;
        }
        ((float4*)out)[(long long)r * 32 + tx] = o;
    }
}

// ---------------- mean pool per graph (batch sorted) ----------------
__device__ __forceinline__ int lower_bound_batch(const void* batch, long long key, int is64) {
    int lo = 0, hi = N_NODES;
    while (lo < hi) {
        int mid = (lo + hi) >> 1;
        long long v = load_idx(batch, mid, is64);
        if (v < key) lo = mid + 1; else hi = mid;
    }
    return lo;
}

__global__ void k_pool(const float* __restrict__ x, const void* __restrict__ batch) {
    int g = blockIdx.x;
    int f = threadIdx.x;
    __shared__ int s_beg, s_end;
    if (f == 0) {
        int is64 = g_is64;
        s_beg = lower_bound_batch(batch, g, is64);
        s_end = lower_bound_batch(batch, g + 1, is64);
    }
    __syncthreads();
    int beg = s_beg, end = s_end;
    float s = 0.f;
    for (int r = beg; r < end; r++) s += x[(long long)r * HID + f];
    float cnt = (float)(end - beg);
    g_pooled[g * HID + f] = s / fmaxf(cnt, 1.0f);
}

// ---------------- head: relu(pooled@W1+b1) @ W2 + b2, log_softmax ----------------
__global__ void k_head(const float* __restrict__ W1, const float* __restrict__ b1,
                       const float* __restrict__ W2, const float* __restrict__ b2,
                       float* __restrict__ out) {
    int g = blockIdx.x;
    int t = threadIdx.x;
    __shared__ float sp[HID], sh[HID], sl[OUT_DIM];
    __shared__ float smax, slse;
    sp[t] = g_pooled[g * HID + t];
    __syncthreads();
    float acc = b1[t];
    #pragma unroll 8
    for (int k = 0; k < HID; k++) acc += sp[k] * W1[k * HID + t];
    sh[t] = fmaxf(acc, 0.f);
    __syncthreads();
    if (t < OUT_DIM) {
        float a = b2[t];
        #pragma unroll 8
        for (int k = 0; k < HID; k++) a += sh[k] * W2[k * OUT_DIM + t];
        sl[t] = a;
    }
    __syncthreads();
    if (t == 0) {
        float m = -1e30f;
        for (int o = 0; o < OUT_DIM; o++) m = fmaxf(m, sl[o]);
        float s = 0.f;
        for (int o = 0; o < OUT_DIM; o++) s += expf(sl[o] - m);
        smax = m; slse = logf(s);
    }
    __syncthreads();
    if (t < OUT_DIM) out[g * OUT_DIM + t] = sl[t] - smax - slse;
}

// ---------------- launch ----------------
extern "C" void kernel_launch(void* const* d_in, const int* in_sizes, int n_in,
                              void* d_out, int out_size) {
    const float* x      = (const float*)d_in[0];
    const void*  edge   = d_in[1];
    const void*  batch  = d_in[2];
    const float* W1s    = (const float*)d_in[3];
    const float* b1s    = (const float*)d_in[4];
    const float* W2s    = (const float*)d_in[5];
    const float* b2s    = (const float*)d_in[6];
    const float* gammas = (const float*)d_in[7];
    const float* betas  = (const float*)d_in[8];
    const float* means  = (const float*)d_in[9];
    const float* vars   = (const float*)d_in[10];
    const float* epsarr = (const float*)d_in[11];
    const float* lin1W  = (const float*)d_in[12];
    const float* lin1b  = (const float*)d_in[13];
    const float* lin2W  = (const float*)d_in[14];
    const float* lin2b  = (const float*)d_in[15];
    float* out = (float*)d_out;

    float *A, *B, *C, *bnsc, *bnsh;
    int *rowoff;
    cudaGetSymbolAddress((void**)&A, g_A);
    cudaGetSymbolAddress((void**)&B, g_B);
    cudaGetSymbolAddress((void**)&C, g_C);
    cudaGetSymbolAddress((void**)&bnsc, g_bnscale);
    cudaGetSymbolAddress((void**)&bnsh, g_bnshift);
    cudaGetSymbolAddress((void**)&rowoff, g_rowoff);

    cudaFuncSetAttribute(k_gemm, cudaFuncAttributeMaxDynamicSharedMemorySize, GEMM_SMEM);

    // index width + CSR build (once per call)
    k_detect<<<1, 32>>>(edge);
    k_zero_int<<<(N_NODES + 1 + 255) / 256, 256>>>(rowoff, N_NODES + 1);
    k_count<<<(N_EDGES + 255) / 256, 256>>>(edge);
    k_scan<<<1, 1024>>>();
    k_fill<<<(N_EDGES + 255) / 256, 256>>>(edge);

    const int gemm_grid = (N_NODES + GBM - 1) / GBM;
    const int agg_blocks = (N_NODES * 32 + 255) / 256;

    const float* cur = x;
    for (int l = 0; l < N_LAYERS; l++) {
        k_agg<<<agg_blocks, 256>>>(cur, B, epsarr, l);
        k_gemm<<<gemm_grid, 256, GEMM_SMEM>>>(B, W1s + l * HID * HID, b1s + l * HID,
                                              C, nullptr, nullptr);
        k_bnprep<<<1, 128>>>(gammas + l * HID, betas + l * HID,
                             means + l * HID, vars + l * HID);
        k_gemm<<<gemm_grid, 256, GEMM_SMEM>>>(C, W2s + l * HID * HID, b2s + l * HID,
                                              A, bnsc, bnsh);
        cur = A;
    }

    k_pool<<<N_GRAPHS, HID>>>(A, batch);
    k_head<<<N_GRAPHS, HID>>>(lin1W, lin1b, lin2W, lin2b, out);
}